// round 8
// baseline (speedup 1.0000x reference)
#include <cuda_runtime.h>
#include <cstdint>

typedef unsigned long long u64;
#define FULLMASK 0xffffffffu

#define MAXN 100000
#define MAXE 1250048  // padded to 64-row tile multiple

// Static scratch (allocation-free rule)
__device__ float g_Q[MAXN * 64];
__device__ float g_K[MAXN * 64];
__device__ float g_V[MAXN * 64];
__device__ uint2 g_WEs[64 * 64];   // WE tf32 (hi,lo) split
__device__ float g_Ef[(size_t)MAXE * 64];
__device__ int g_cnt[MAXN];
__device__ int g_off[MAXN + 1];
__device__ int g_pos[MAXN];
__device__ int g_bsum[256];
__device__ int g_perm[MAXE];
__device__ int g_psrc[MAXE];

// ---------------- helpers ----------------
__device__ __forceinline__ u64 ffma2(u64 a, u64 b, u64 c) {
    u64 d;
    asm("fma.rn.f32x2 %0, %1, %2, %3;" : "=l"(d) : "l"(a), "l"(b), "l"(c));
    return d;
}
__device__ __forceinline__ float2 unpack2(u64 v) {
    float lo, hi;
    asm("mov.b64 {%0,%1}, %2;" : "=f"(lo), "=f"(hi) : "l"(v));
    return make_float2(lo, hi);
}
__device__ __forceinline__ void lds_2xu64(u64& a, u64& b, uint32_t saddr) {
    asm volatile("ld.shared.v2.u64 {%0,%1}, [%2];" : "=l"(a), "=l"(b) : "r"(saddr));
}
__device__ __forceinline__ uint32_t tf32_rna(float f) {
    uint32_t r;
    asm("cvt.rna.tf32.f32 %0, %1;" : "=r"(r) : "f"(f));
    return r;
}
__device__ __forceinline__ uint32_t smem_u32(const void* p) {
    return (uint32_t)__cvta_generic_to_shared(p);
}
__device__ __forceinline__ uint2 split_tf32(float f) {
    uint32_t hi = tf32_rna(f);
    float lo = f - __uint_as_float(hi);
    return make_uint2(hi, tf32_rna(lo));
}
__device__ __forceinline__ void mma_tf32(float* c, uint32_t a0, uint32_t a1,
                                         uint32_t a2, uint32_t a3, uint32_t b0,
                                         uint32_t b1) {
    asm volatile(
        "mma.sync.aligned.m16n8k8.row.col.f32.tf32.tf32.f32 "
        "{%0,%1,%2,%3}, {%4,%5,%6,%7}, {%8,%9}, {%0,%1,%2,%3};"
        : "+f"(c[0]), "+f"(c[1]), "+f"(c[2]), "+f"(c[3])
        : "r"(a0), "r"(a1), "r"(a2), "r"(a3), "r"(b0), "r"(b1));
}

// ---------------- kernel 1: proj Q/K/V + WE split + cnt zero ----------------
__global__ __launch_bounds__(256) void ex_projzero_kernel(
    const float* __restrict__ x,
    const float* __restrict__ WQ, const float* __restrict__ WK,
    const float* __restrict__ WV, const float* __restrict__ WE, int n) {
    int gidx = blockIdx.x * 256 + threadIdx.x;
    if (gidx < n) g_cnt[gidx] = 0;
    if (gidx < 4096) g_WEs[gidx] = split_tf32(WE[gidx]);

    __shared__ float Wt[3][64][64];
    for (int idx = threadIdx.x; idx < 3 * 4096; idx += 256) {
        int m = idx >> 12;
        int r = idx & 4095;
        int c = r >> 6, j = r & 63;
        const float* wsrc = (m == 0) ? WQ : (m == 1) ? WK : WV;
        Wt[m][j][c] = wsrc[r];
    }
    __syncthreads();

    int node = gidx;
    if (node >= n) return;

    u64 xq[32];
    const ulonglong2* xp = (const ulonglong2*)(x + (size_t)node * 64);
#pragma unroll
    for (int k = 0; k < 16; k++) {
        ulonglong2 t = xp[k];
        xq[2 * k] = t.x;
        xq[2 * k + 1] = t.y;
    }
    uint32_t wt0 = smem_u32(&Wt[0][0][0]);

#pragma unroll 1
    for (int m = 0; m < 3; m++) {
        float* op = ((m == 0) ? g_Q : (m == 1) ? g_K : g_V) + (size_t)node * 64;
        uint32_t wtm = wt0 + m * 16384;
#pragma unroll 1
        for (int jg = 0; jg < 8; jg++) {
            uint32_t ga = wtm + jg * 2048;
            u64 acc[8];
#pragma unroll
            for (int jj = 0; jj < 8; jj++) acc[jj] = 0ull;
#pragma unroll
            for (int c4 = 0; c4 < 16; c4++) {
#pragma unroll
                for (int jj = 0; jj < 8; jj++) {
                    u64 w0, w1;
                    lds_2xu64(w0, w1, ga + jj * 256 + c4 * 16);
                    acc[jj] = ffma2(xq[2 * c4], w0, acc[jj]);
                    acc[jj] = ffma2(xq[2 * c4 + 1], w1, acc[jj]);
                }
            }
            float v[8];
#pragma unroll
            for (int jj = 0; jj < 8; jj++) {
                float2 e = unpack2(acc[jj]);
                v[jj] = e.x + e.y;
            }
            ((float4*)(op + jg * 8))[0] = make_float4(v[0], v[1], v[2], v[3]);
            ((float4*)(op + jg * 8))[1] = make_float4(v[4], v[5], v[6], v[7]);
        }
    }
}

// ---------------- counting sort by dst ----------------
__global__ void ex_hist_kernel(const int* __restrict__ eidx, int ne) {
    const int* dstA = eidx + ne;
    for (int e = blockIdx.x * blockDim.x + threadIdx.x; e < ne;
         e += gridDim.x * blockDim.x)
        atomicAdd(&g_cnt[__ldg(dstA + e)], 1);
}

// per-block sums over 512-count chunks
__global__ void ex_scan1_kernel(int n) {
    __shared__ int s[256];
    int i0 = blockIdx.x * 512 + threadIdx.x * 2;
    int a = (i0 < n) ? g_cnt[i0] : 0;
    int b = (i0 + 1 < n) ? g_cnt[i0 + 1] : 0;
    s[threadIdx.x] = a + b;
    __syncthreads();
#pragma unroll
    for (int st = 128; st > 0; st >>= 1) {
        if (threadIdx.x < st) s[threadIdx.x] += s[threadIdx.x + st];
        __syncthreads();
    }
    if (threadIdx.x == 0) g_bsum[blockIdx.x] = s[0];
}

// exclusive scan of block sums (single block)
__global__ void ex_scan2_kernel(int nb, int ne, int n) {
    __shared__ int s[256];
    int v = (threadIdx.x < nb) ? g_bsum[threadIdx.x] : 0;
    s[threadIdx.x] = v;
    __syncthreads();
#pragma unroll
    for (int st = 1; st < 256; st <<= 1) {
        int t = (threadIdx.x >= st) ? s[threadIdx.x - st] : 0;
        __syncthreads();
        s[threadIdx.x] += t;
        __syncthreads();
    }
    int ex = (threadIdx.x == 0) ? 0 : s[threadIdx.x - 1];
    if (threadIdx.x < nb) g_bsum[threadIdx.x] = ex;
    if (threadIdx.x == 0) g_off[n] = ne;
}

// per-chunk exclusive scan + base -> g_off, g_pos
__global__ void ex_scan3_kernel(int n) {
    __shared__ int ps[256];
    int i0 = blockIdx.x * 512 + threadIdx.x * 2;
    int a = (i0 < n) ? g_cnt[i0] : 0;
    int b = (i0 + 1 < n) ? g_cnt[i0 + 1] : 0;
    ps[threadIdx.x] = a + b;
    __syncthreads();
#pragma unroll
    for (int st = 1; st < 256; st <<= 1) {
        int t = (threadIdx.x >= st) ? ps[threadIdx.x - st] : 0;
        __syncthreads();
        ps[threadIdx.x] += t;
        __syncthreads();
    }
    int excl = ((threadIdx.x == 0) ? 0 : ps[threadIdx.x - 1]) + g_bsum[blockIdx.x];
    if (i0 < n) { g_off[i0] = excl; g_pos[i0] = excl; }
    if (i0 + 1 < n) { g_off[i0 + 1] = excl + a; g_pos[i0 + 1] = excl + a; }
}

__global__ void ex_scatter_kernel(const int* __restrict__ eidx, int ne) {
    const int* srcA = eidx;
    const int* dstA = eidx + ne;
    for (int e = blockIdx.x * blockDim.x + threadIdx.x; e < ne;
         e += gridDim.x * blockDim.x) {
        int dst = __ldg(dstA + e);
        int src = __ldg(srcA + e);
        int pos = atomicAdd(&g_pos[dst], 1);
        g_perm[pos] = e;
        g_psrc[pos] = src;
    }
}

// ---------------- Ef GEMM (3xTF32 mma.sync), 64-row tiles, sorted order -------
// A rows = edge_attr[perm[...]]; Ef stored in SORTED order (sequential).
#define GM_B 34816
#define GM_TOT 69632

__global__ __launch_bounds__(128) void ex_gemm_kernel(
    const float* __restrict__ ea, int ne) {
    extern __shared__ char smem[];
    uint2* a_s = (uint2*)smem;
    uint2* b_s = (uint2*)(smem + GM_B);

    int tid = threadIdx.x;
    int wid = tid >> 5, lane = tid & 31;
    int g = lane >> 2, tg = lane & 3;
    int e0 = blockIdx.x << 6;

#pragma unroll
    for (int i = 0; i < 32; i++) {
        int idx = tid + i * 128;
        b_s[(idx >> 6) * 68 + (idx & 63)] = g_WEs[idx];
    }
    {
        float4 z4 = make_float4(0.f, 0.f, 0.f, 0.f);
#pragma unroll
        for (int i = 0; i < 8; i++) {
            int idx = tid + i * 128;
            int row = idx >> 4, c4 = idx & 15;
            int e = e0 + row;
            float4 v = z4;
            if (e < ne) {
                int er = __ldg(g_perm + e);
                v = __ldcs((const float4*)(ea + (size_t)er * 64) + c4);
            }
            uint2* ap = a_s + row * 68 + c4 * 4;
            ap[0] = split_tf32(v.x);
            ap[1] = split_tf32(v.y);
            ap[2] = split_tf32(v.z);
            ap[3] = split_tf32(v.w);
        }
    }
    __syncthreads();

    int m0 = wid << 4;
    float acc[8][4];
#pragma unroll
    for (int nt = 0; nt < 8; nt++)
#pragma unroll
        for (int j = 0; j < 4; j++) acc[nt][j] = 0.f;

#pragma unroll
    for (int kt = 0; kt < 8; kt++) {
        int k0 = kt << 3;
        uint2 A0 = a_s[(m0 + g) * 68 + k0 + tg];
        uint2 A1 = a_s[(m0 + g + 8) * 68 + k0 + tg];
        uint2 A2 = a_s[(m0 + g) * 68 + k0 + tg + 4];
        uint2 A3 = a_s[(m0 + g + 8) * 68 + k0 + tg + 4];
#pragma unroll
        for (int nt = 0; nt < 8; nt++) {
            uint2 B0 = b_s[(k0 + tg) * 68 + (nt << 3) + g];
            uint2 B1 = b_s[(k0 + tg + 4) * 68 + (nt << 3) + g];
            mma_tf32(acc[nt], A0.x, A1.x, A2.x, A3.x, B0.x, B1.x);  // hi*hi
            mma_tf32(acc[nt], A0.x, A1.x, A2.x, A3.x, B0.y, B1.y);  // hi*lo
            mma_tf32(acc[nt], A0.y, A1.y, A2.y, A3.y, B0.x, B1.x);  // lo*hi
        }
    }

    int r0 = e0 + m0 + g;
    int r1 = r0 + 8;
    float* p0 = g_Ef + (size_t)r0 * 64 + 2 * tg;
    float* p1 = g_Ef + (size_t)r1 * 64 + 2 * tg;
    if (r0 < ne) {
#pragma unroll
        for (int nt = 0; nt < 8; nt++)
            __stcs((float2*)(p0 + (nt << 3)), make_float2(acc[nt][0], acc[nt][1]));
    }
    if (r1 < ne) {
#pragma unroll
        for (int nt = 0; nt < 8; nt++)
            __stcs((float2*)(p1 + (nt << 3)), make_float2(acc[nt][2], acc[nt][3]));
    }
}

// ---------------- edge kernel: warp-per-node segmented reduce (NO atomics) ----
__global__ __launch_bounds__(256) void ex_edge_kernel(
    float* __restrict__ out, int n) {
    int warp = threadIdx.x >> 5, lane = threadIdx.x & 31;
    int gw = blockIdx.x * 8 + warp;
    int nw = gridDim.x * 8;

    for (int d = gw; d < n; d += nw) {
        int j0 = __ldg(g_off + d);
        int j1 = __ldg(g_off + d + 1);
        float2 q2 = __ldg((const float2*)(g_Q + (size_t)d * 64) + lane);

        float ax = 0.f, ay = 0.f, z = 0.f;
        for (int j = j0; j < j1; j++) {
            int src = __ldg(g_psrc + j);
            float2 ef = __ldcs((const float2*)(g_Ef + (size_t)j * 64) + lane);
            float2 k2 = __ldg((const float2*)(g_K + (size_t)src * 64) + lane);
            float2 v2 = __ldg((const float2*)(g_V + (size_t)src * 64) + lane);
            float part = k2.x * q2.x * ef.x + k2.y * q2.y * ef.y;
            part += __shfl_xor_sync(FULLMASK, part, 1);
            part += __shfl_xor_sync(FULLMASK, part, 2);
            float s = part * 0.35355339059327373f;  // 1/sqrt(8)
            s = fminf(5.0f, fmaxf(-5.0f, s));
            float sc = __expf(s);
            ax = fmaf(v2.x, sc, ax);
            ay = fmaf(v2.y, sc, ay);
            z += sc;
        }
        float inv = __frcp_rn(z + 1e-6f);
        ((float2*)(out + (size_t)d * 64))[lane] = make_float2(ax * inv, ay * inv);
    }
}

extern "C" void kernel_launch(void* const* d_in, const int* in_sizes, int n_in,
                              void* d_out, int out_size) {
    const float* x  = (const float*)d_in[0];
    const float* ea = (const float*)d_in[1];
    const float* WQ = (const float*)d_in[2];
    const float* WK = (const float*)d_in[3];
    const float* WV = (const float*)d_in[4];
    const float* WE = (const float*)d_in[5];
    const int* eidx = (const int*)d_in[6];
    float* out = (float*)d_out;

    int n  = in_sizes[0] / 64;
    int ne = in_sizes[6] / 2;
    int ntiles = (ne + 63) >> 6;
    int nb = (n + 511) >> 9;  // scan chunks

    cudaFuncSetAttribute(ex_gemm_kernel,
                         cudaFuncAttributeMaxDynamicSharedMemorySize, GM_TOT);

    ex_projzero_kernel<<<(n + 255) / 256, 256>>>(x, WQ, WK, WV, WE, n);
    ex_hist_kernel<<<1024, 256>>>(eidx, ne);
    ex_scan1_kernel<<<nb, 256>>>(n);
    ex_scan2_kernel<<<1, 256>>>(nb, ne, n);
    ex_scan3_kernel<<<nb, 256>>>(n);
    ex_scatter_kernel<<<1024, 256>>>(eidx, ne);
    ex_gemm_kernel<<<ntiles, 128, GM_TOT>>>(ea, ne);
    ex_edge_kernel<<<800, 256>>>(out, n);
}